// round 13
// baseline (speedup 1.0000x reference)
#include <cuda_runtime.h>
#include <math.h>

#define T_TOK 2048
#define NE 8
#define TOPK 2
#define HD 2048
#define ID 1408
#define ISD 5632
#define NSLOT (T_TOK * TOPK)

#define BM 128
#define BN 64
#define BK 16
#define SSTR 20   // smem row stride in floats (16 + 4 pad)

#define WSLOT 23068672   // floats = NE*ID*HD = 2*ISD*HD (exact identities)

// ---------------- scratch (static device globals; ~212 MB, proven size) ------
__device__ float d_Hs[(size_t)T_TOK * ISD];      // shared hidden (tf32-rounded)
__device__ float d_Hr[(size_t)NSLOT * ID];       // routed hidden (compact rows)
__device__ float d_Y [(size_t)NSLOT * HD];       // routed down output (compact)
__device__ float d_xr[(size_t)T_TOK * HD];       // tf32-rounded activations
__device__ float d_Wr[(size_t)WSLOT];            // 92.3 MB weight scratch
__device__ int   d_tok[NE * T_TOK];
__device__ float d_wt [NE * T_TOK];
__device__ int   d_cnt[NE];
__device__ int   d_off[NE];
__device__ int   d_slot[T_TOK * TOPK];
__device__ int   d_topki[T_TOK * TOPK];
__device__ float d_topkw[T_TOK * TOPK];

// ---------------- small PTX helpers ------------------------------------------
__device__ __forceinline__ unsigned smem_u32(const void* p) {
    return (unsigned)__cvta_generic_to_shared(p);
}
__device__ __forceinline__ void cp16(unsigned dst, const void* src) {
    asm volatile("cp.async.cg.shared.global [%0], [%1], 16;\n" :: "r"(dst), "l"(src));
}
__device__ __forceinline__ void cp_commit() { asm volatile("cp.async.commit_group;\n"); }
template <int N>
__device__ __forceinline__ void cp_wait() { asm volatile("cp.async.wait_group %0;\n" :: "n"(N)); }
__device__ __forceinline__ unsigned f2tf(float f) {
    unsigned r; asm("cvt.rna.tf32.f32 %0, %1;" : "=r"(r) : "f"(f)); return r;
}
// operands pre-rounded to tf32-RNA: raw f32 bits, hardware truncation is exact
__device__ __forceinline__ void mma1688(float c[4], const unsigned a[4], const unsigned b[2]) {
    asm volatile(
        "mma.sync.aligned.m16n8k8.row.col.f32.tf32.tf32.f32 "
        "{%0,%1,%2,%3},{%4,%5,%6,%7},{%8,%9},{%0,%1,%2,%3};\n"
        : "+f"(c[0]), "+f"(c[1]), "+f"(c[2]), "+f"(c[3])
        : "r"(a[0]), "r"(a[1]), "r"(a[2]), "r"(a[3]), "r"(b[0]), "r"(b[1]));
}
__device__ __forceinline__ float silu_mul(float g, float u) {
    return g / (1.f + expf(-g)) * u;
}

// ---------------- tf32 pre-round (RNA) ----------------------------------------
// weights -> d_Wr at float4 offset dstOff4
__global__ void round_kw(const float4* __restrict__ src, int n4, int dstOff4)
{
    int i = blockIdx.x * blockDim.x + threadIdx.x;
    if (i >= n4) return;
    float4 v = src[i], o;
    o.x = __uint_as_float(f2tf(v.x));
    o.y = __uint_as_float(f2tf(v.y));
    o.z = __uint_as_float(f2tf(v.z));
    o.w = __uint_as_float(f2tf(v.w));
    ((float4*)d_Wr)[dstOff4 + i] = o;
}
// activations -> d_xr
__global__ void round_kx(const float4* __restrict__ src, int n4)
{
    int i = blockIdx.x * blockDim.x + threadIdx.x;
    if (i >= n4) return;
    float4 v = src[i], o;
    o.x = __uint_as_float(f2tf(v.x));
    o.y = __uint_as_float(f2tf(v.y));
    o.z = __uint_as_float(f2tf(v.z));
    o.w = __uint_as_float(f2tf(v.w));
    ((float4*)d_xr)[i] = o;
}

// ---------------- routing (exact fp32 x) --------------------------------------
__global__ void route_kernel(const float* __restrict__ x, const float* __restrict__ gw)
{
    int warp = (blockIdx.x * blockDim.x + threadIdx.x) >> 5;
    int lane = threadIdx.x & 31;
    if (warp >= T_TOK) return;
    const float* xr = x + (size_t)warp * HD;

    float s[NE];
#pragma unroll
    for (int e = 0; e < NE; e++) s[e] = 0.f;
    for (int k = lane; k < HD; k += 32) {
        float xv = xr[k];
#pragma unroll
        for (int e = 0; e < NE; e++) s[e] += xv * gw[e * HD + k];
    }
#pragma unroll
    for (int e = 0; e < NE; e++)
#pragma unroll
        for (int off = 16; off; off >>= 1)
            s[e] += __shfl_down_sync(0xffffffffu, s[e], off);

    if (lane == 0) {
        float mx = s[0];
#pragma unroll
        for (int e = 1; e < NE; e++) mx = fmaxf(mx, s[e]);
        float g[NE], sum = 0.f;
#pragma unroll
        for (int e = 0; e < NE; e++) { g[e] = expf(s[e] - mx); sum += g[e]; }
        float inv = 1.f / sum;
#pragma unroll
        for (int e = 0; e < NE; e++) g[e] *= inv;
        int i0 = 0; float v0 = g[0];
#pragma unroll
        for (int e = 1; e < NE; e++) if (g[e] > v0) { v0 = g[e]; i0 = e; }
        int i1 = -1; float v1 = -1.f;
#pragma unroll
        for (int e = 0; e < NE; e++) if (e != i0 && g[e] > v1) { v1 = g[e]; i1 = e; }
        float dn = 1.f / (v0 + v1);
        d_topki[warp * 2 + 0] = i0;  d_topkw[warp * 2 + 0] = v0 * dn;
        d_topki[warp * 2 + 1] = i1;  d_topkw[warp * 2 + 1] = v1 * dn;
    }
}

// ------- deterministic compaction with global (cross-expert) offsets ----------
__global__ void build_kernel()
{
    int e = blockIdx.x;
    int tid = threadIdx.x;
    int lane = tid & 31, w = tid >> 5;
    __shared__ int warp_sums[8];
    __shared__ int s_base;
    __shared__ int s_off;

    int cl = 0;
    for (int j = tid; j < T_TOK * TOPK; j += 256) cl += (d_topki[j] < e) ? 1 : 0;
#pragma unroll
    for (int o = 16; o; o >>= 1) cl += __shfl_down_sync(0xffffffffu, cl, o);
    if (lane == 0) warp_sums[w] = cl;
    __syncthreads();
    if (tid == 0) {
        int t = 0;
        for (int i = 0; i < 8; i++) t += warp_sums[i];
        s_off = t; s_base = 0; d_off[e] = t;
    }
    __syncthreads();

    for (int c = 0; c < T_TOK; c += 256) {
        int t = c + tid;
        int k = -1;
        if (d_topki[2 * t] == e) k = 0;
        else if (d_topki[2 * t + 1] == e) k = 1;
        int flag = (k >= 0) ? 1 : 0;
        unsigned bal = __ballot_sync(0xffffffffu, flag);
        int pre = __popc(bal & ((1u << lane) - 1u));
        if (lane == 31) warp_sums[w] = pre + flag;
        __syncthreads();
        int wbase = 0;
        for (int i = 0; i < w; i++) wbase += warp_sums[i];
        int pos = s_base + wbase + pre;
        if (flag) {
            d_tok [e * T_TOK + pos] = t;
            d_wt  [e * T_TOK + pos] = d_topkw[2 * t + k];
            d_slot[2 * t + k]       = s_off + pos;
        }
        __syncthreads();
        if (tid == 0) {
            int tot = 0;
            for (int i = 0; i < 8; i++) tot += warp_sums[i];
            s_base += tot;
        }
        __syncthreads();
    }
    if (tid == 0) d_cnt[e] = s_base;
}

// ================= fused TF32 MMA gate+up with SiLU epilogue ==================
// Exact R2 loop structure; NO cvt in hot loop (operands pre-rounded RNA).
// Bg = d_Wr, Bu = d_Wr + buOff. ze = expert index (arg, not blockIdx.z).
template <bool EXPERT>
__global__ __launch_bounds__(256, 1)
void swiglu_mma_k(int ze, int N, int Kd, int buOff)
{
    const int z = EXPERT ? ze : 0;
    const float* A  = d_xr;
    const float* Bg = d_Wr;
    const float* Bu = d_Wr + (size_t)buOff;
    const int M = EXPERT ? d_cnt[z] : T_TOK;
    const int off = EXPERT ? d_off[z] : 0;
    float* C = EXPERT ? (d_Hr + (size_t)off * N) : d_Hs;

    const int row0 = blockIdx.y * BM;
    if (row0 >= M) return;
    const int col0 = blockIdx.x * BN;

    __shared__ float As [2][BM * SSTR];
    __shared__ float Bgs[2][BN * SSTR];
    __shared__ float Bus[2][BN * SSTR];

    const int tid = threadIdx.x, lane = tid & 31, warp = tid >> 5;
    const int wm = warp >> 1, wn = warp & 1;
    const int gr = lane >> 2, gc = lane & 3;

    const int ar1 = tid >> 2, ar2 = 64 + (tid >> 2);
    const int kc  = (tid & 3) * 4;
    int r1 = row0 + ar1, r2 = row0 + ar2;
    int g1 = (r1 < M) ? (EXPERT ? d_tok[z * T_TOK + r1] : r1) : 0;
    int g2 = (r2 < M) ? (EXPERT ? d_tok[z * T_TOK + r2] : r2) : 0;
    const float* Ap1 = A + (size_t)g1 * Kd + kc;
    const float* Ap2 = A + (size_t)g2 * Kd + kc;
    const int br = tid >> 2;
    const float* Bgp = Bg + (size_t)(col0 + br) * Kd + kc;
    const float* Bup = Bu + (size_t)(col0 + br) * Kd + kc;

    unsigned sa1[2], sa2[2], sbg[2], sbu[2];
#pragma unroll
    for (int s = 0; s < 2; s++) {
        sa1[s] = smem_u32(&As [s][ar1 * SSTR + kc]);
        sa2[s] = smem_u32(&As [s][ar2 * SSTR + kc]);
        sbg[s] = smem_u32(&Bgs[s][br  * SSTR + kc]);
        sbu[s] = smem_u32(&Bus[s][br  * SSTR + kc]);
    }

    float accg[2][4][4] = {}, accu[2][4][4] = {};

    const int Kt = Kd / BK;
    cp16(sa1[0], Ap1); cp16(sa2[0], Ap2);
    cp16(sbg[0], Bgp); cp16(sbu[0], Bup);
    cp_commit();

    for (int kt = 0; kt < Kt; kt++) {
        const int cur = kt & 1, nxt = cur ^ 1;
        if (kt + 1 < Kt) {
            const int ko = (kt + 1) * BK;
            cp16(sa1[nxt], Ap1 + ko); cp16(sa2[nxt], Ap2 + ko);
            cp16(sbg[nxt], Bgp + ko); cp16(sbu[nxt], Bup + ko);
            cp_commit();
            cp_wait<1>();
        } else {
            cp_wait<0>();
        }
        __syncthreads();

        const float* as  = As [cur];
        const float* bgs = Bgs[cur];
        const float* bus = Bus[cur];
#pragma unroll
        for (int ks = 0; ks < 2; ks++) {
            const int k = ks * 8;
            unsigned afr[2][4];
#pragma unroll
            for (int mt = 0; mt < 2; mt++) {
                const int mb = wm * 32 + mt * 16;
                afr[mt][0] = __float_as_uint(as[(mb + gr    ) * SSTR + k + gc    ]);
                afr[mt][1] = __float_as_uint(as[(mb + gr + 8) * SSTR + k + gc    ]);
                afr[mt][2] = __float_as_uint(as[(mb + gr    ) * SSTR + k + gc + 4]);
                afr[mt][3] = __float_as_uint(as[(mb + gr + 8) * SSTR + k + gc + 4]);
            }
#pragma unroll
            for (int nt = 0; nt < 4; nt++) {
                const int nb = wn * 32 + nt * 8;
                unsigned bg[2], bu[2];
                bg[0] = __float_as_uint(bgs[(nb + gr) * SSTR + k + gc    ]);
                bg[1] = __float_as_uint(bgs[(nb + gr) * SSTR + k + gc + 4]);
                bu[0] = __float_as_uint(bus[(nb + gr) * SSTR + k + gc    ]);
                bu[1] = __float_as_uint(bus[(nb + gr) * SSTR + k + gc + 4]);
#pragma unroll
                for (int mt = 0; mt < 2; mt++) {
                    mma1688(accg[mt][nt], afr[mt], bg);
                    mma1688(accu[mt][nt], afr[mt], bu);
                }
            }
        }
        __syncthreads();
    }

    // epilogue: silu(g)*u rounded to tf32 (down-GEMM truncation then exact)
#pragma unroll
    for (int mt = 0; mt < 2; mt++) {
        const int mlo = row0 + wm * 32 + mt * 16 + gr;
        const int mhi = mlo + 8;
#pragma unroll
        for (int nt = 0; nt < 4; nt++) {
            const int n = col0 + wn * 32 + nt * 8 + gc * 2;
            if (mlo < M) {
                float2 v;
                v.x = __uint_as_float(f2tf(silu_mul(accg[mt][nt][0], accu[mt][nt][0])));
                v.y = __uint_as_float(f2tf(silu_mul(accg[mt][nt][1], accu[mt][nt][1])));
                *(float2*)(C + (size_t)mlo * N + n) = v;
            }
            if (mhi < M) {
                float2 v;
                v.x = __uint_as_float(f2tf(silu_mul(accg[mt][nt][2], accu[mt][nt][2])));
                v.y = __uint_as_float(f2tf(silu_mul(accg[mt][nt][3], accu[mt][nt][3])));
                *(float2*)(C + (size_t)mhi * N + n) = v;
            }
        }
    }
}

// ================= TF32 MMA down-projection (cvt-free) ========================
template <bool EXPERT>
__global__ __launch_bounds__(256, 1)
void down_mma_k(float* __restrict__ Cout, int N, int Kd)
{
    const int z = EXPERT ? blockIdx.z : 0;
    const int M = EXPERT ? d_cnt[z] : T_TOK;
    const int off = EXPERT ? d_off[z] : 0;
    const float* A = EXPERT ? (d_Hr + (size_t)off * Kd) : d_Hs;
    const float* B = d_Wr + (size_t)z * N * Kd;
    float* C = EXPERT ? (d_Y + (size_t)off * N) : Cout;

    const int row0 = blockIdx.y * BM;
    if (row0 >= M) return;
    const int col0 = blockIdx.x * BN;

    __shared__ float As[2][BM * SSTR];
    __shared__ float Bs[2][BN * SSTR];

    const int tid = threadIdx.x, lane = tid & 31, warp = tid >> 5;
    const int wm = warp >> 1, wn = warp & 1;
    const int gr = lane >> 2, gc = lane & 3;

    const int ar1 = tid >> 2, ar2 = 64 + (tid >> 2);
    const int kc  = (tid & 3) * 4;
    int r1 = row0 + ar1, r2 = row0 + ar2;
    const float* Ap1 = A + (size_t)((r1 < M) ? r1 : 0) * Kd + kc;
    const float* Ap2 = A + (size_t)((r2 < M) ? r2 : 0) * Kd + kc;
    const int br = tid >> 2;
    const float* Bp = B + (size_t)(col0 + br) * Kd + kc;

    unsigned sa1[2], sa2[2], sb[2];
#pragma unroll
    for (int s = 0; s < 2; s++) {
        sa1[s] = smem_u32(&As[s][ar1 * SSTR + kc]);
        sa2[s] = smem_u32(&As[s][ar2 * SSTR + kc]);
        sb [s] = smem_u32(&Bs[s][br  * SSTR + kc]);
    }

    float acc[2][4][4] = {};

    const int Kt = Kd / BK;
    cp16(sa1[0], Ap1); cp16(sa2[0], Ap2); cp16(sb[0], Bp);
    cp_commit();

    for (int kt = 0; kt < Kt; kt++) {
        const int cur = kt & 1, nxt = cur ^ 1;
        if (kt + 1 < Kt) {
            const int ko = (kt + 1) * BK;
            cp16(sa1[nxt], Ap1 + ko); cp16(sa2[nxt], Ap2 + ko); cp16(sb[nxt], Bp + ko);
            cp_commit();
            cp_wait<1>();
        } else {
            cp_wait<0>();
        }
        __syncthreads();

        const float* as = As[cur];
        const float* bs = Bs[cur];
#pragma unroll
        for (int ks = 0; ks < 2; ks++) {
            const int k = ks * 8;
            unsigned afr[2][4];
#pragma unroll
            for (int mt = 0; mt < 2; mt++) {
                const int mb = wm * 32 + mt * 16;
                afr[mt][0] = __float_as_uint(as[(mb + gr    ) * SSTR + k + gc    ]);
                afr[mt][1] = __float_as_uint(as[(mb + gr + 8) * SSTR + k + gc    ]);
                afr[mt][2] = __float_as_uint(as[(mb + gr    ) * SSTR + k + gc + 4]);
                afr[mt][3] = __float_as_uint(as[(mb + gr + 8) * SSTR + k + gc + 4]);
            }
#pragma unroll
            for (int nt = 0; nt < 4; nt++) {
                const int nb = wn * 32 + nt * 8;
                unsigned bf[2];
                bf[0] = __float_as_uint(bs[(nb + gr) * SSTR + k + gc    ]);
                bf[1] = __float_as_uint(bs[(nb + gr) * SSTR + k + gc + 4]);
#pragma unroll
                for (int mt = 0; mt < 2; mt++)
                    mma1688(acc[mt][nt], afr[mt], bf);
            }
        }
        __syncthreads();
    }

#pragma unroll
    for (int mt = 0; mt < 2; mt++) {
        const int mlo = row0 + wm * 32 + mt * 16 + gr;
        const int mhi = mlo + 8;
        float slo = 1.f, shi = 1.f;
        if (EXPERT) {
            if (mlo < M) slo = d_wt[z * T_TOK + mlo];
            if (mhi < M) shi = d_wt[z * T_TOK + mhi];
        }
#pragma unroll
        for (int nt = 0; nt < 4; nt++) {
            const int n = col0 + wn * 32 + nt * 8 + gc * 2;
            if (mlo < M)
                *(float2*)(C + (size_t)mlo * N + n) =
                    make_float2(acc[mt][nt][0] * slo, acc[mt][nt][1] * slo);
            if (mhi < M)
                *(float2*)(C + (size_t)mhi * N + n) =
                    make_float2(acc[mt][nt][2] * shi, acc[mt][nt][3] * shi);
        }
    }
}

// ---------------- final combine ----------------------------------------------
__global__ void combine_kernel(float* __restrict__ out)
{
    int idx = blockIdx.x * blockDim.x + threadIdx.x;
    int t  = idx / (HD / 4);
    int h4 = idx % (HD / 4);
    int s0 = d_slot[2 * t], s1 = d_slot[2 * t + 1];
    float4 o = ((float4*)out)[idx];
    float4 a = ((const float4*)(d_Y + (size_t)s0 * HD))[h4];
    float4 b = ((const float4*)(d_Y + (size_t)s1 * HD))[h4];
    o.x += a.x + b.x;  o.y += a.y + b.y;  o.z += a.z + b.z;  o.w += a.w + b.w;
    ((float4*)out)[idx] = o;
}

// ---------------- launcher ---------------------------------------------------
extern "C" void kernel_launch(void* const* d_in, const int* in_sizes, int n_in,
                              void* d_out, int out_size)
{
    const float* x   = (const float*)d_in[0];
    const float* gw  = (const float*)d_in[1];
    const float* egw = (const float*)d_in[2];
    const float* euw = (const float*)d_in[3];
    const float* edw = (const float*)d_in[4];
    const float* sgw = (const float*)d_in[5];
    const float* suw = (const float*)d_in[6];
    const float* sdw = (const float*)d_in[7];
    float* out = (float*)d_out;

    const int n4x = T_TOK * HD / 4;          // activations
    const int n4s = ISD * HD / 4;            // one shared weight (46 MB)
    const int n4e1 = ID * HD / 4;            // one routed expert weight (11.5 MB)
    const int n4eA = NE * ID * HD / 4;       // all routed down weights (92 MB)

    // routing + compaction (exact fp32 inputs)
    route_kernel<<<T_TOK * 32 / 256, 256>>>(x, gw);
    build_kernel<<<NE, 256>>>();

    // activations -> tf32 (RNA)
    round_kx<<<(n4x + 255) / 256, 256>>>((const float4*)x, n4x);

    // shared fused gate+up: both weights fit the scratch (2*ISD*HD = WSLOT)
    round_kw<<<(n4s + 255) / 256, 256>>>((const float4*)sgw, n4s, 0);
    round_kw<<<(n4s + 255) / 256, 256>>>((const float4*)suw, n4s, n4s);
    swiglu_mma_k<false><<<dim3(ISD / BN, T_TOK / BM, 1), 256>>>(0, ISD, HD, ISD * HD);

    // routed fused gate+up: per-expert (each pair = 2*ID*HD floats in scratch)
    for (int e = 0; e < NE; e++) {
        round_kw<<<(n4e1 + 255) / 256, 256>>>((const float4*)(egw + (size_t)e * ID * HD), n4e1, 0);
        round_kw<<<(n4e1 + 255) / 256, 256>>>((const float4*)(euw + (size_t)e * ID * HD), n4e1, n4e1);
        swiglu_mma_k<true><<<dim3(ID / BN, T_TOK / BM, 1), 256>>>(e, ID, HD, ID * HD);
    }

    // shared down -> out (full overwrite)
    round_kw<<<(n4s + 255) / 256, 256>>>((const float4*)sdw, n4s, 0);
    down_mma_k<false><<<dim3(HD / BN, T_TOK / BM, 1), 256>>>(out, HD, ISD);

    // routed down (all experts fit: NE*HD*ID = WSLOT), combine weight folded
    round_kw<<<(n4eA + 255) / 256, 256>>>((const float4*)edw, n4eA, 0);
    down_mma_k<true><<<dim3(HD / BN, T_TOK / BM, NE), 256>>>(nullptr, HD, ID);

    combine_kernel<<<(T_TOK * HD / 4) / 256, 256>>>(out);
}

// round 14
// speedup vs baseline: 1.6472x; 1.6472x over previous
#include <cuda_runtime.h>
#include <cuda_fp16.h>
#include <math.h>

#define T_TOK 2048
#define NE 8
#define TOPK 2
#define HD 2048
#define ID 1408
#define ISD 5632
#define NSLOT (T_TOK * TOPK)

#define BM 128
#define BN 64
#define BK 16
#define SSTRH 24   // smem row stride in halves (16 + 8 pad) -> conflict-free frags

// ---------------- scratch (static device globals; ~103 MB) -------------------
__device__ float d_Hs[(size_t)T_TOK * ISD];      // shared hidden (fp32)
__device__ float d_Hr[(size_t)NSLOT * ID];       // routed hidden (compact rows)
__device__ float d_Y [(size_t)NSLOT * HD];       // routed down output (compact)
__device__ int   d_tok[NE * T_TOK];
__device__ float d_wt [NE * T_TOK];
__device__ int   d_cnt[NE];
__device__ int   d_off[NE];
__device__ int   d_slot[T_TOK * TOPK];
__device__ int   d_topki[T_TOK * TOPK];
__device__ float d_topkw[T_TOK * TOPK];

// ---------------- helpers -----------------------------------------------------
__device__ __forceinline__ unsigned pack_h2(float lo, float hi) {
    unsigned r;
    asm("cvt.rn.f16x2.f32 %0, %1, %2;" : "=r"(r) : "f"(hi), "f"(lo));
    return r;
}
// f32.f16.f16.f32 m16n8k16
__device__ __forceinline__ void mma16816(float c[4], const unsigned a[4], const unsigned b[2]) {
    asm volatile(
        "mma.sync.aligned.m16n8k16.row.col.f32.f16.f16.f32 "
        "{%0,%1,%2,%3},{%4,%5,%6,%7},{%8,%9},{%0,%1,%2,%3};\n"
        : "+f"(c[0]), "+f"(c[1]), "+f"(c[2]), "+f"(c[3])
        : "r"(a[0]), "r"(a[1]), "r"(a[2]), "r"(a[3]), "r"(b[0]), "r"(b[1]));
}
__device__ __forceinline__ float silu_mul(float g, float u) {
    return g / (1.f + expf(-g)) * u;
}
__device__ __forceinline__ float4 ldg4(const float* p) { return *(const float4*)p; }
__device__ __forceinline__ void sts_h4(__half* dst, float4 v) {
    uint2 u;
    u.x = pack_h2(v.x, v.y);
    u.y = pack_h2(v.z, v.w);
    *(uint2*)dst = u;
}
__device__ __forceinline__ unsigned ldsh2(const __half* p) { return *(const unsigned*)p; }

// ---------------- routing (exact fp32 x) --------------------------------------
__global__ void route_kernel(const float* __restrict__ x, const float* __restrict__ gw)
{
    int warp = (blockIdx.x * blockDim.x + threadIdx.x) >> 5;
    int lane = threadIdx.x & 31;
    if (warp >= T_TOK) return;
    const float* xr = x + (size_t)warp * HD;

    float s[NE];
#pragma unroll
    for (int e = 0; e < NE; e++) s[e] = 0.f;
    for (int k = lane; k < HD; k += 32) {
        float xv = xr[k];
#pragma unroll
        for (int e = 0; e < NE; e++) s[e] += xv * gw[e * HD + k];
    }
#pragma unroll
    for (int e = 0; e < NE; e++)
#pragma unroll
        for (int off = 16; off; off >>= 1)
            s[e] += __shfl_down_sync(0xffffffffu, s[e], off);

    if (lane == 0) {
        float mx = s[0];
#pragma unroll
        for (int e = 1; e < NE; e++) mx = fmaxf(mx, s[e]);
        float g[NE], sum = 0.f;
#pragma unroll
        for (int e = 0; e < NE; e++) { g[e] = expf(s[e] - mx); sum += g[e]; }
        float inv = 1.f / sum;
#pragma unroll
        for (int e = 0; e < NE; e++) g[e] *= inv;
        int i0 = 0; float v0 = g[0];
#pragma unroll
        for (int e = 1; e < NE; e++) if (g[e] > v0) { v0 = g[e]; i0 = e; }
        int i1 = -1; float v1 = -1.f;
#pragma unroll
        for (int e = 0; e < NE; e++) if (e != i0 && g[e] > v1) { v1 = g[e]; i1 = e; }
        float dn = 1.f / (v0 + v1);
        d_topki[warp * 2 + 0] = i0;  d_topkw[warp * 2 + 0] = v0 * dn;
        d_topki[warp * 2 + 1] = i1;  d_topkw[warp * 2 + 1] = v1 * dn;
    }
}

// ------- deterministic compaction with global (cross-expert) offsets ----------
__global__ void build_kernel()
{
    int e = blockIdx.x;
    int tid = threadIdx.x;
    int lane = tid & 31, w = tid >> 5;
    __shared__ int warp_sums[8];
    __shared__ int s_base;
    __shared__ int s_off;

    int cl = 0;
    for (int j = tid; j < T_TOK * TOPK; j += 256) cl += (d_topki[j] < e) ? 1 : 0;
#pragma unroll
    for (int o = 16; o; o >>= 1) cl += __shfl_down_sync(0xffffffffu, cl, o);
    if (lane == 0) warp_sums[w] = cl;
    __syncthreads();
    if (tid == 0) {
        int t = 0;
        for (int i = 0; i < 8; i++) t += warp_sums[i];
        s_off = t; s_base = 0; d_off[e] = t;
    }
    __syncthreads();

    for (int c = 0; c < T_TOK; c += 256) {
        int t = c + tid;
        int k = -1;
        if (d_topki[2 * t] == e) k = 0;
        else if (d_topki[2 * t + 1] == e) k = 1;
        int flag = (k >= 0) ? 1 : 0;
        unsigned bal = __ballot_sync(0xffffffffu, flag);
        int pre = __popc(bal & ((1u << lane) - 1u));
        if (lane == 31) warp_sums[w] = pre + flag;
        __syncthreads();
        int wbase = 0;
        for (int i = 0; i < w; i++) wbase += warp_sums[i];
        int pos = s_base + wbase + pre;
        if (flag) {
            d_tok [e * T_TOK + pos] = t;
            d_wt  [e * T_TOK + pos] = d_topkw[2 * t + k];
            d_slot[2 * t + k]       = s_off + pos;
        }
        __syncthreads();
        if (tid == 0) {
            int tot = 0;
            for (int i = 0; i < 8; i++) tot += warp_sums[i];
            s_base += tot;
        }
        __syncthreads();
    }
    if (tid == 0) d_cnt[e] = s_base;
}

// ================= FP16 MMA fused gate+up with SiLU epilogue ==================
// f32 gmem -> cvt.rn.f16x2 at STS; register-staged double buffer; 1 sync/iter.
template <bool EXPERT>
__global__ __launch_bounds__(256, 2)
void swiglu_mma_k(const float* __restrict__ A,
                  const float* __restrict__ Bg_all,
                  const float* __restrict__ Bu_all,
                  int N, int Kd)
{
    const int z = EXPERT ? blockIdx.z : 0;
    const float* Bg = Bg_all + (size_t)z * N * Kd;
    const float* Bu = Bu_all + (size_t)z * N * Kd;
    const int M = EXPERT ? d_cnt[z] : T_TOK;
    const int off = EXPERT ? d_off[z] : 0;
    float* C = EXPERT ? (d_Hr + (size_t)off * N) : d_Hs;

    const int row0 = blockIdx.y * BM;
    if (row0 >= M) return;
    const int col0 = blockIdx.x * BN;

    __shared__ __half As [2][BM * SSTRH];
    __shared__ __half Bgs[2][BN * SSTRH];
    __shared__ __half Bus[2][BN * SSTRH];

    const int tid = threadIdx.x, lane = tid & 31, warp = tid >> 5;
    const int wm = warp >> 1, wn = warp & 1;
    const int gr = lane >> 2, gc = lane & 3;

    // loader: thread owns A rows (tid>>2, 64+tid>>2), B row tid>>2, k-chunk (tid&3)*4
    const int lr = tid >> 2;
    const int kc = (tid & 3) * 4;
    int r1 = row0 + lr, r2 = row0 + 64 + lr;
    int g1 = (r1 < M) ? (EXPERT ? d_tok[z * T_TOK + r1] : r1) : 0;
    int g2 = (r2 < M) ? (EXPERT ? d_tok[z * T_TOK + r2] : r2) : 0;
    const float* Ap1 = A + (size_t)g1 * Kd + kc;
    const float* Ap2 = A + (size_t)g2 * Kd + kc;
    const float* Bgp = Bg + (size_t)(col0 + lr) * Kd + kc;
    const float* Bup = Bu + (size_t)(col0 + lr) * Kd + kc;

    __half* sA1[2]; __half* sA2[2]; __half* sBg[2]; __half* sBu[2];
#pragma unroll
    for (int s = 0; s < 2; s++) {
        sA1[s] = &As [s][ lr       * SSTRH + kc];
        sA2[s] = &As [s][(64 + lr) * SSTRH + kc];
        sBg[s] = &Bgs[s][ lr       * SSTRH + kc];
        sBu[s] = &Bus[s][ lr       * SSTRH + kc];
    }

    float accg[2][4][4] = {}, accu[2][4][4] = {};

    const int Kt = Kd / BK;
    // prologue: tile0 -> smem buf0; tile1 -> staged regs
    {
        float4 a1 = ldg4(Ap1), a2 = ldg4(Ap2), bg = ldg4(Bgp), bu = ldg4(Bup);
        sts_h4(sA1[0], a1); sts_h4(sA2[0], a2);
        sts_h4(sBg[0], bg); sts_h4(sBu[0], bu);
    }
    float4 st_a1 = ldg4(Ap1 + BK), st_a2 = ldg4(Ap2 + BK);
    float4 st_bg = ldg4(Bgp + BK), st_bu = ldg4(Bup + BK);

    for (int kt = 0; kt < Kt; kt++) {
        const int cur = kt & 1, nxt = cur ^ 1;
        __syncthreads();   // STS(cur) visible; compute(kt-1) done -> nxt free

        if (kt + 1 < Kt) {
            sts_h4(sA1[nxt], st_a1); sts_h4(sA2[nxt], st_a2);
            sts_h4(sBg[nxt], st_bg); sts_h4(sBu[nxt], st_bu);
        }
        if (kt + 2 < Kt) {
            const int ko = (kt + 2) * BK;
            st_a1 = ldg4(Ap1 + ko); st_a2 = ldg4(Ap2 + ko);
            st_bg = ldg4(Bgp + ko); st_bu = ldg4(Bup + ko);
        }

        const __half* as  = As [cur];
        const __half* bgs = Bgs[cur];
        const __half* bus = Bus[cur];

        unsigned afr[2][4];
#pragma unroll
        for (int mt = 0; mt < 2; mt++) {
            const int mb = wm * 32 + mt * 16;
            afr[mt][0] = ldsh2(&as[(mb + gr    ) * SSTRH + 2 * gc    ]);
            afr[mt][1] = ldsh2(&as[(mb + gr + 8) * SSTRH + 2 * gc    ]);
            afr[mt][2] = ldsh2(&as[(mb + gr    ) * SSTRH + 2 * gc + 8]);
            afr[mt][3] = ldsh2(&as[(mb + gr + 8) * SSTRH + 2 * gc + 8]);
        }
#pragma unroll
        for (int nt = 0; nt < 4; nt++) {
            const int nb = wn * 32 + nt * 8;
            unsigned bg[2], bu[2];
            bg[0] = ldsh2(&bgs[(nb + gr) * SSTRH + 2 * gc    ]);
            bg[1] = ldsh2(&bgs[(nb + gr) * SSTRH + 2 * gc + 8]);
            bu[0] = ldsh2(&bus[(nb + gr) * SSTRH + 2 * gc    ]);
            bu[1] = ldsh2(&bus[(nb + gr) * SSTRH + 2 * gc + 8]);
#pragma unroll
            for (int mt = 0; mt < 2; mt++) {
                mma16816(accg[mt][nt], afr[mt], bg);
                mma16816(accu[mt][nt], afr[mt], bu);
            }
        }
    }

    // epilogue: silu(g)*u (fp32)
#pragma unroll
    for (int mt = 0; mt < 2; mt++) {
        const int mlo = row0 + wm * 32 + mt * 16 + gr;
        const int mhi = mlo + 8;
#pragma unroll
        for (int nt = 0; nt < 4; nt++) {
            const int n = col0 + wn * 32 + nt * 8 + gc * 2;
            if (mlo < M) {
                float2 v;
                v.x = silu_mul(accg[mt][nt][0], accu[mt][nt][0]);
                v.y = silu_mul(accg[mt][nt][1], accu[mt][nt][1]);
                *(float2*)(C + (size_t)mlo * N + n) = v;
            }
            if (mhi < M) {
                float2 v;
                v.x = silu_mul(accg[mt][nt][2], accu[mt][nt][2]);
                v.y = silu_mul(accg[mt][nt][3], accu[mt][nt][3]);
                *(float2*)(C + (size_t)mhi * N + n) = v;
            }
        }
    }
}

// ================= FP16 MMA down-projection ===================================
template <bool EXPERT>
__global__ __launch_bounds__(256, 2)
void down_mma_k(const float* __restrict__ B_all, float* __restrict__ Cout,
                int N, int Kd)
{
    const int z = EXPERT ? blockIdx.z : 0;
    const int M = EXPERT ? d_cnt[z] : T_TOK;
    const int off = EXPERT ? d_off[z] : 0;
    const float* A = EXPERT ? (d_Hr + (size_t)off * Kd) : d_Hs;
    const float* B = B_all + (size_t)z * N * Kd;
    float* C = EXPERT ? (d_Y + (size_t)off * N) : Cout;

    const int row0 = blockIdx.y * BM;
    if (row0 >= M) return;
    const int col0 = blockIdx.x * BN;

    __shared__ __half As[2][BM * SSTRH];
    __shared__ __half Bs[2][BN * SSTRH];

    const int tid = threadIdx.x, lane = tid & 31, warp = tid >> 5;
    const int wm = warp >> 1, wn = warp & 1;
    const int gr = lane >> 2, gc = lane & 3;

    const int lr = tid >> 2;
    const int kc = (tid & 3) * 4;
    int r1 = row0 + lr, r2 = row0 + 64 + lr;
    const float* Ap1 = A + (size_t)((r1 < M) ? r1 : 0) * Kd + kc;
    const float* Ap2 = A + (size_t)((r2 < M) ? r2 : 0) * Kd + kc;
    const float* Bp  = B + (size_t)(col0 + lr) * Kd + kc;

    __half* sA1[2]; __half* sA2[2]; __half* sB[2];
#pragma unroll
    for (int s = 0; s < 2; s++) {
        sA1[s] = &As[s][ lr       * SSTRH + kc];
        sA2[s] = &As[s][(64 + lr) * SSTRH + kc];
        sB [s] = &Bs[s][ lr       * SSTRH + kc];
    }

    float acc[2][4][4] = {};

    const int Kt = Kd / BK;
    {
        float4 a1 = ldg4(Ap1), a2 = ldg4(Ap2), b = ldg4(Bp);
        sts_h4(sA1[0], a1); sts_h4(sA2[0], a2); sts_h4(sB[0], b);
    }
    float4 st_a1 = ldg4(Ap1 + BK), st_a2 = ldg4(Ap2 + BK), st_b = ldg4(Bp + BK);

    for (int kt = 0; kt < Kt; kt++) {
        const int cur = kt & 1, nxt = cur ^ 1;
        __syncthreads();

        if (kt + 1 < Kt) {
            sts_h4(sA1[nxt], st_a1); sts_h4(sA2[nxt], st_a2); sts_h4(sB[nxt], st_b);
        }
        if (kt + 2 < Kt) {
            const int ko = (kt + 2) * BK;
            st_a1 = ldg4(Ap1 + ko); st_a2 = ldg4(Ap2 + ko); st_b = ldg4(Bp + ko);
        }

        const __half* as = As[cur];
        const __half* bs = Bs[cur];

        unsigned afr[2][4];
#pragma unroll
        for (int mt = 0; mt < 2; mt++) {
            const int mb = wm * 32 + mt * 16;
            afr[mt][0] = ldsh2(&as[(mb + gr    ) * SSTRH + 2 * gc    ]);
            afr[mt][1] = ldsh2(&as[(mb + gr + 8) * SSTRH + 2 * gc    ]);
            afr[mt][2] = ldsh2(&as[(mb + gr    ) * SSTRH + 2 * gc + 8]);
            afr[mt][3] = ldsh2(&as[(mb + gr + 8) * SSTRH + 2 * gc + 8]);
        }
#pragma unroll
        for (int nt = 0; nt < 4; nt++) {
            const int nb = wn * 32 + nt * 8;
            unsigned bf[2];
            bf[0] = ldsh2(&bs[(nb + gr) * SSTRH + 2 * gc    ]);
            bf[1] = ldsh2(&bs[(nb + gr) * SSTRH + 2 * gc + 8]);
#pragma unroll
            for (int mt = 0; mt < 2; mt++)
                mma16816(acc[mt][nt], afr[mt], bf);
        }
    }

#pragma unroll
    for (int mt = 0; mt < 2; mt++) {
        const int mlo = row0 + wm * 32 + mt * 16 + gr;
        const int mhi = mlo + 8;
        float slo = 1.f, shi = 1.f;
        if (EXPERT) {
            if (mlo < M) slo = d_wt[z * T_TOK + mlo];
            if (mhi < M) shi = d_wt[z * T_TOK + mhi];
        }
#pragma unroll
        for (int nt = 0; nt < 4; nt++) {
            const int n = col0 + wn * 32 + nt * 8 + gc * 2;
            if (mlo < M)
                *(float2*)(C + (size_t)mlo * N + n) =
                    make_float2(acc[mt][nt][0] * slo, acc[mt][nt][1] * slo);
            if (mhi < M)
                *(float2*)(C + (size_t)mhi * N + n) =
                    make_float2(acc[mt][nt][2] * shi, acc[mt][nt][3] * shi);
        }
    }
}

// ---------------- final combine ----------------------------------------------
__global__ void combine_kernel(float* __restrict__ out)
{
    int idx = blockIdx.x * blockDim.x + threadIdx.x;
    int t  = idx / (HD / 4);
    int h4 = idx % (HD / 4);
    int s0 = d_slot[2 * t], s1 = d_slot[2 * t + 1];
    float4 o = ((float4*)out)[idx];
    float4 a = ((const float4*)(d_Y + (size_t)s0 * HD))[h4];
    float4 b = ((const float4*)(d_Y + (size_t)s1 * HD))[h4];
    o.x += a.x + b.x;  o.y += a.y + b.y;  o.z += a.z + b.z;  o.w += a.w + b.w;
    ((float4*)out)[idx] = o;
}

// ---------------- launcher ---------------------------------------------------
extern "C" void kernel_launch(void* const* d_in, const int* in_sizes, int n_in,
                              void* d_out, int out_size)
{
    const float* x   = (const float*)d_in[0];
    const float* gw  = (const float*)d_in[1];
    const float* egw = (const float*)d_in[2];
    const float* euw = (const float*)d_in[3];
    const float* edw = (const float*)d_in[4];
    const float* sgw = (const float*)d_in[5];
    const float* suw = (const float*)d_in[6];
    const float* sdw = (const float*)d_in[7];
    float* out = (float*)d_out;

    route_kernel<<<T_TOK * 32 / 256, 256>>>(x, gw);
    build_kernel<<<NE, 256>>>();

    // shared gate+up: M=2048, N=5632, K=2048
    swiglu_mma_k<false><<<dim3(ISD / BN, T_TOK / BM, 1), 256>>>(x, sgw, suw, ISD, HD);
    // routed gate+up (gathered, compact rows): N=1408, K=2048
    swiglu_mma_k<true ><<<dim3(ID  / BN, T_TOK / BM, NE), 256>>>(x, egw, euw, ID, HD);
    // shared down: M=2048, N=2048, K=5632 -> out (full overwrite)
    down_mma_k<false><<<dim3(HD / BN, T_TOK / BM, 1), 256>>>(sdw, out, HD, ISD);
    // routed down (combine weight folded): N=2048, K=1408
    down_mma_k<true ><<<dim3(HD / BN, T_TOK / BM, NE), 256>>>(edw, nullptr, HD, ID);

    combine_kernel<<<(T_TOK * HD / 4) / 256, 256>>>(out);
}

// round 16
// speedup vs baseline: 2.3261x; 1.4122x over previous
#include <cuda_runtime.h>
#include <cuda_fp16.h>
#include <math.h>

#define T_TOK 2048
#define NE 8
#define TOPK 2
#define HD 2048
#define ID 1408
#define ISD 5632
#define NSLOT (T_TOK * TOPK)

#define BM 128
#define BN 64
#define BK 16
#define SSTRH 24   // smem row stride in halves (48B) -> conflict-free LDSM phases

// ---------------- scratch (static device globals; ~103 MB) -------------------
__device__ float d_Hs[(size_t)T_TOK * ISD];
__device__ float d_Hr[(size_t)NSLOT * ID];
__device__ float d_Y [(size_t)NSLOT * HD];
__device__ int   d_tok[NE * T_TOK];
__device__ float d_wt [NE * T_TOK];
__device__ int   d_cnt[NE];
__device__ int   d_off[NE];
__device__ int   d_slot[T_TOK * TOPK];
__device__ int   d_topki[T_TOK * TOPK];
__device__ float d_topkw[T_TOK * TOPK];

// ---------------- helpers -----------------------------------------------------
__device__ __forceinline__ unsigned smem_u32(const void* p) {
    return (unsigned)__cvta_generic_to_shared(p);
}
__device__ __forceinline__ unsigned pack_h2(float lo, float hi) {
    unsigned r;
    asm("cvt.rn.f16x2.f32 %0, %1, %2;" : "=r"(r) : "f"(hi), "f"(lo));
    return r;
}
__device__ __forceinline__ void mma16816(float c[4], const unsigned a[4], const unsigned b[2]) {
    asm volatile(
        "mma.sync.aligned.m16n8k16.row.col.f32.f16.f16.f32 "
        "{%0,%1,%2,%3},{%4,%5,%6,%7},{%8,%9},{%0,%1,%2,%3};\n"
        : "+f"(c[0]), "+f"(c[1]), "+f"(c[2]), "+f"(c[3])
        : "r"(a[0]), "r"(a[1]), "r"(a[2]), "r"(a[3]), "r"(b[0]), "r"(b[1]));
}
__device__ __forceinline__ void ldsm_x4(unsigned r[4], unsigned saddr) {
    asm volatile("ldmatrix.sync.aligned.m8n8.x4.shared.b16 {%0,%1,%2,%3}, [%4];\n"
                 : "=r"(r[0]), "=r"(r[1]), "=r"(r[2]), "=r"(r[3]) : "r"(saddr));
}
__device__ __forceinline__ float silu_mul(float g, float u) {
    return g / (1.f + expf(-g)) * u;
}
__device__ __forceinline__ float4 ldg4(const float* p) { return *(const float4*)p; }
__device__ __forceinline__ void sts_h4(__half* dst, float4 v) {
    uint2 u;
    u.x = pack_h2(v.x, v.y);
    u.y = pack_h2(v.z, v.w);
    *(uint2*)dst = u;
}

// ---------------- routing (exact fp32 x) --------------------------------------
__global__ void route_kernel(const float* __restrict__ x, const float* __restrict__ gw)
{
    int warp = (blockIdx.x * blockDim.x + threadIdx.x) >> 5;
    int lane = threadIdx.x & 31;
    if (warp >= T_TOK) return;
    const float* xr = x + (size_t)warp * HD;

    float s[NE];
#pragma unroll
    for (int e = 0; e < NE; e++) s[e] = 0.f;
    for (int k = lane; k < HD; k += 32) {
        float xv = xr[k];
#pragma unroll
        for (int e = 0; e < NE; e++) s[e] += xv * gw[e * HD + k];
    }
#pragma unroll
    for (int e = 0; e < NE; e++)
#pragma unroll
        for (int off = 16; off; off >>= 1)
            s[e] += __shfl_down_sync(0xffffffffu, s[e], off);

    if (lane == 0) {
        float mx = s[0];
#pragma unroll
        for (int e = 1; e < NE; e++) mx = fmaxf(mx, s[e]);
        float g[NE], sum = 0.f;
#pragma unroll
        for (int e = 0; e < NE; e++) { g[e] = expf(s[e] - mx); sum += g[e]; }
        float inv = 1.f / sum;
#pragma unroll
        for (int e = 0; e < NE; e++) g[e] *= inv;
        int i0 = 0; float v0 = g[0];
#pragma unroll
        for (int e = 1; e < NE; e++) if (g[e] > v0) { v0 = g[e]; i0 = e; }
        int i1 = -1; float v1 = -1.f;
#pragma unroll
        for (int e = 0; e < NE; e++) if (e != i0 && g[e] > v1) { v1 = g[e]; i1 = e; }
        float dn = 1.f / (v0 + v1);
        d_topki[warp * 2 + 0] = i0;  d_topkw[warp * 2 + 0] = v0 * dn;
        d_topki[warp * 2 + 1] = i1;  d_topkw[warp * 2 + 1] = v1 * dn;
    }
}

// ------- deterministic compaction with global (cross-expert) offsets ----------
__global__ void build_kernel()
{
    int e = blockIdx.x;
    int tid = threadIdx.x;
    int lane = tid & 31, w = tid >> 5;
    __shared__ int warp_sums[8];
    __shared__ int s_base;
    __shared__ int s_off;

    int cl = 0;
    for (int j = tid; j < T_TOK * TOPK; j += 256) cl += (d_topki[j] < e) ? 1 : 0;
#pragma unroll
    for (int o = 16; o; o >>= 1) cl += __shfl_down_sync(0xffffffffu, cl, o);
    if (lane == 0) warp_sums[w] = cl;
    __syncthreads();
    if (tid == 0) {
        int t = 0;
        for (int i = 0; i < 8; i++) t += warp_sums[i];
        s_off = t; s_base = 0; d_off[e] = t;
    }
    __syncthreads();

    for (int c = 0; c < T_TOK; c += 256) {
        int t = c + tid;
        int k = -1;
        if (d_topki[2 * t] == e) k = 0;
        else if (d_topki[2 * t + 1] == e) k = 1;
        int flag = (k >= 0) ? 1 : 0;
        unsigned bal = __ballot_sync(0xffffffffu, flag);
        int pre = __popc(bal & ((1u << lane) - 1u));
        if (lane == 31) warp_sums[w] = pre + flag;
        __syncthreads();
        int wbase = 0;
        for (int i = 0; i < w; i++) wbase += warp_sums[i];
        int pos = s_base + wbase + pre;
        if (flag) {
            d_tok [e * T_TOK + pos] = t;
            d_wt  [e * T_TOK + pos] = d_topkw[2 * t + k];
            d_slot[2 * t + k]       = s_off + pos;
        }
        __syncthreads();
        if (tid == 0) {
            int tot = 0;
            for (int i = 0; i < 8; i++) tot += warp_sums[i];
            s_base += tot;
        }
        __syncthreads();
    }
    if (tid == 0) d_cnt[e] = s_base;
}

// ================= FP16 MMA fused gate+up with SiLU epilogue ==================
// cvt at STS; register-staged double buffer; ldmatrix fragment loads.
template <bool EXPERT>
__global__ __launch_bounds__(256, 2)
void swiglu_mma_k(const float* __restrict__ A,
                  const float* __restrict__ Bg_all,
                  const float* __restrict__ Bu_all,
                  int N, int Kd)
{
    const int z = EXPERT ? blockIdx.z : 0;
    const float* Bg = Bg_all + (size_t)z * N * Kd;
    const float* Bu = Bu_all + (size_t)z * N * Kd;
    const int M = EXPERT ? d_cnt[z] : T_TOK;
    const int off = EXPERT ? d_off[z] : 0;
    float* C = EXPERT ? (d_Hr + (size_t)off * N) : d_Hs;

    const int row0 = blockIdx.y * BM;
    if (row0 >= M) return;
    const int col0 = blockIdx.x * BN;

    __shared__ __align__(16) __half As [2][BM * SSTRH];
    __shared__ __align__(16) __half Bgs[2][BN * SSTRH];
    __shared__ __align__(16) __half Bus[2][BN * SSTRH];

    const int tid = threadIdx.x, lane = tid & 31, warp = tid >> 5;
    const int wm = warp >> 1, wn = warp & 1;
    const int gr = lane >> 2, gc = lane & 3;

    // loader
    const int lr = tid >> 2;
    const int kc = (tid & 3) * 4;
    int r1 = row0 + lr, r2 = row0 + 64 + lr;
    int g1 = (r1 < M) ? (EXPERT ? d_tok[z * T_TOK + r1] : r1) : 0;
    int g2 = (r2 < M) ? (EXPERT ? d_tok[z * T_TOK + r2] : r2) : 0;
    const float* Ap1 = A + (size_t)g1 * Kd + kc;
    const float* Ap2 = A + (size_t)g2 * Kd + kc;
    const float* Bgp = Bg + (size_t)(col0 + lr) * Kd + kc;
    const float* Bup = Bu + (size_t)(col0 + lr) * Kd + kc;

    __half* sA1[2]; __half* sA2[2]; __half* sBg[2]; __half* sBu[2];
#pragma unroll
    for (int s = 0; s < 2; s++) {
        sA1[s] = &As [s][ lr       * SSTRH + kc];
        sA2[s] = &As [s][(64 + lr) * SSTRH + kc];
        sBg[s] = &Bgs[s][ lr       * SSTRH + kc];
        sBu[s] = &Bus[s][ lr       * SSTRH + kc];
    }

    // ldmatrix per-lane addresses
    unsigned aAd[2][2], gAd[2][2], uAd[2][2];
    {
        const int arow = (lane & 7) + ((lane >> 3) & 1) * 8;
        const int akof = (lane >> 4) * 8;
        const int brow = (lane & 7) + (lane >> 4) * 8;
        const int bkof = ((lane >> 3) & 1) * 8;
#pragma unroll
        for (int s = 0; s < 2; s++)
#pragma unroll
            for (int i = 0; i < 2; i++) {
                aAd[s][i] = smem_u32(&As [s][(wm * 32 + i * 16 + arow) * SSTRH + akof]);
                gAd[s][i] = smem_u32(&Bgs[s][(wn * 32 + i * 16 + brow) * SSTRH + bkof]);
                uAd[s][i] = smem_u32(&Bus[s][(wn * 32 + i * 16 + brow) * SSTRH + bkof]);
            }
    }

    float accg[2][4][4] = {}, accu[2][4][4] = {};

    const int Kt = Kd / BK;
    {
        float4 a1 = ldg4(Ap1), a2 = ldg4(Ap2), bg = ldg4(Bgp), bu = ldg4(Bup);
        sts_h4(sA1[0], a1); sts_h4(sA2[0], a2);
        sts_h4(sBg[0], bg); sts_h4(sBu[0], bu);
    }
    float4 st_a1 = ldg4(Ap1 + BK), st_a2 = ldg4(Ap2 + BK);
    float4 st_bg = ldg4(Bgp + BK), st_bu = ldg4(Bup + BK);

    for (int kt = 0; kt < Kt; kt++) {
        const int cur = kt & 1, nxt = cur ^ 1;
        __syncthreads();   // STS(cur) visible; compute(kt-1) done -> nxt free

        if (kt + 1 < Kt) {
            sts_h4(sA1[nxt], st_a1); sts_h4(sA2[nxt], st_a2);
            sts_h4(sBg[nxt], st_bg); sts_h4(sBu[nxt], st_bu);
        }
        if (kt + 2 < Kt) {
            const int ko = (kt + 2) * BK;
            st_a1 = ldg4(Ap1 + ko); st_a2 = ldg4(Ap2 + ko);
            st_bg = ldg4(Bgp + ko); st_bu = ldg4(Bup + ko);
        }

        unsigned afr[2][4], bgf[2][4], buf[2][4];
        ldsm_x4(afr[0], aAd[cur][0]);
        ldsm_x4(afr[1], aAd[cur][1]);
        ldsm_x4(bgf[0], gAd[cur][0]);   // regs: (nt0,k0),(nt0,k8),(nt1,k0),(nt1,k8)
        ldsm_x4(bgf[1], gAd[cur][1]);
        ldsm_x4(buf[0], uAd[cur][0]);
        ldsm_x4(buf[1], uAd[cur][1]);

#pragma unroll
        for (int p = 0; p < 2; p++) {
#pragma unroll
            for (int q = 0; q < 2; q++) {
                const int nt = p * 2 + q;
                unsigned bg[2] = { bgf[p][q * 2], bgf[p][q * 2 + 1] };
                unsigned bu[2] = { buf[p][q * 2], buf[p][q * 2 + 1] };
#pragma unroll
                for (int mt = 0; mt < 2; mt++) {
                    mma16816(accg[mt][nt], afr[mt], bg);
                    mma16816(accu[mt][nt], afr[mt], bu);
                }
            }
        }
    }

    // epilogue: silu(g)*u (fp32)
#pragma unroll
    for (int mt = 0; mt < 2; mt++) {
        const int mlo = row0 + wm * 32 + mt * 16 + gr;
        const int mhi = mlo + 8;
#pragma unroll
        for (int nt = 0; nt < 4; nt++) {
            const int n = col0 + wn * 32 + nt * 8 + gc * 2;
            if (mlo < M) {
                float2 v;
                v.x = silu_mul(accg[mt][nt][0], accu[mt][nt][0]);
                v.y = silu_mul(accg[mt][nt][1], accu[mt][nt][1]);
                *(float2*)(C + (size_t)mlo * N + n) = v;
            }
            if (mhi < M) {
                float2 v;
                v.x = silu_mul(accg[mt][nt][2], accu[mt][nt][2]);
                v.y = silu_mul(accg[mt][nt][3], accu[mt][nt][3]);
                *(float2*)(C + (size_t)mhi * N + n) = v;
            }
        }
    }
}

// ================= FP16 MMA down-projection ===================================
template <bool EXPERT>
__global__ __launch_bounds__(256, 2)
void down_mma_k(const float* __restrict__ B_all, float* __restrict__ Cout,
                int N, int Kd)
{
    const int z = EXPERT ? blockIdx.z : 0;
    const int M = EXPERT ? d_cnt[z] : T_TOK;
    const int off = EXPERT ? d_off[z] : 0;
    const float* A = EXPERT ? (d_Hr + (size_t)off * Kd) : d_Hs;
    const float* B = B_all + (size_t)z * N * Kd;
    float* C = EXPERT ? (d_Y + (size_t)off * N) : Cout;

    const int row0 = blockIdx.y * BM;
    if (row0 >= M) return;
    const int col0 = blockIdx.x * BN;

    __shared__ __align__(16) __half As[2][BM * SSTRH];
    __shared__ __align__(16) __half Bs[2][BN * SSTRH];

    const int tid = threadIdx.x, lane = tid & 31, warp = tid >> 5;
    const int wm = warp >> 1, wn = warp & 1;
    const int gr = lane >> 2, gc = lane & 3;

    const int lr = tid >> 2;
    const int kc = (tid & 3) * 4;
    int r1 = row0 + lr, r2 = row0 + 64 + lr;
    const float* Ap1 = A + (size_t)((r1 < M) ? r1 : 0) * Kd + kc;
    const float* Ap2 = A + (size_t)((r2 < M) ? r2 : 0) * Kd + kc;
    const float* Bp  = B + (size_t)(col0 + lr) * Kd + kc;

    __half* sA1[2]; __half* sA2[2]; __half* sB[2];
#pragma unroll
    for (int s = 0; s < 2; s++) {
        sA1[s] = &As[s][ lr       * SSTRH + kc];
        sA2[s] = &As[s][(64 + lr) * SSTRH + kc];
        sB [s] = &Bs[s][ lr       * SSTRH + kc];
    }

    unsigned aAd[2][2], bAd[2][2];
    {
        const int arow = (lane & 7) + ((lane >> 3) & 1) * 8;
        const int akof = (lane >> 4) * 8;
        const int brow = (lane & 7) + (lane >> 4) * 8;
        const int bkof = ((lane >> 3) & 1) * 8;
#pragma unroll
        for (int s = 0; s < 2; s++)
#pragma unroll
            for (int i = 0; i < 2; i++) {
                aAd[s][i] = smem_u32(&As[s][(wm * 32 + i * 16 + arow) * SSTRH + akof]);
                bAd[s][i] = smem_u32(&Bs[s][(wn * 32 + i * 16 + brow) * SSTRH + bkof]);
            }
    }

    float acc[2][4][4] = {};

    const int Kt = Kd / BK;
    {
        float4 a1 = ldg4(Ap1), a2 = ldg4(Ap2), b = ldg4(Bp);
        sts_h4(sA1[0], a1); sts_h4(sA2[0], a2); sts_h4(sB[0], b);
    }
    float4 st_a1 = ldg4(Ap1 + BK), st_a2 = ldg4(Ap2 + BK), st_b = ldg4(Bp + BK);

    for (int kt = 0; kt < Kt; kt++) {
        const int cur = kt & 1, nxt = cur ^ 1;
        __syncthreads();

        if (kt + 1 < Kt) {
            sts_h4(sA1[nxt], st_a1); sts_h4(sA2[nxt], st_a2); sts_h4(sB[nxt], st_b);
        }
        if (kt + 2 < Kt) {
            const int ko = (kt + 2) * BK;
            st_a1 = ldg4(Ap1 + ko); st_a2 = ldg4(Ap2 + ko); st_b = ldg4(Bp + ko);
        }

        unsigned afr[2][4], bf[2][4];
        ldsm_x4(afr[0], aAd[cur][0]);
        ldsm_x4(afr[1], aAd[cur][1]);
        ldsm_x4(bf[0], bAd[cur][0]);
        ldsm_x4(bf[1], bAd[cur][1]);

#pragma unroll
        for (int p = 0; p < 2; p++) {
#pragma unroll
            for (int q = 0; q < 2; q++) {
                const int nt = p * 2 + q;
                unsigned bb[2] = { bf[p][q * 2], bf[p][q * 2 + 1] };
#pragma unroll
                for (int mt = 0; mt < 2; mt++)
                    mma16816(acc[mt][nt], afr[mt], bb);
            }
        }
    }

#pragma unroll
    for (int mt = 0; mt < 2; mt++) {
        const int mlo = row0 + wm * 32 + mt * 16 + gr;
        const int mhi = mlo + 8;
        float slo = 1.f, shi = 1.f;
        if (EXPERT) {
            if (mlo < M) slo = d_wt[z * T_TOK + mlo];
            if (mhi < M) shi = d_wt[z * T_TOK + mhi];
        }
#pragma unroll
        for (int nt = 0; nt < 4; nt++) {
            const int n = col0 + wn * 32 + nt * 8 + gc * 2;
            if (mlo < M)
                *(float2*)(C + (size_t)mlo * N + n) =
                    make_float2(acc[mt][nt][0] * slo, acc[mt][nt][1] * slo);
            if (mhi < M)
                *(float2*)(C + (size_t)mhi * N + n) =
                    make_float2(acc[mt][nt][2] * shi, acc[mt][nt][3] * shi);
        }
    }
}

// ---------------- final combine ----------------------------------------------
__global__ void combine_kernel(float* __restrict__ out)
{
    int idx = blockIdx.x * blockDim.x + threadIdx.x;
    int t  = idx / (HD / 4);
    int h4 = idx % (HD / 4);
    int s0 = d_slot[2 * t], s1 = d_slot[2 * t + 1];
    float4 o = ((float4*)out)[idx];
    float4 a = ((const float4*)(d_Y + (size_t)s0 * HD))[h4];
    float4 b = ((const float4*)(d_Y + (size_t)s1 * HD))[h4];
    o.x += a.x + b.x;  o.y += a.y + b.y;  o.z += a.z + b.z;  o.w += a.w + b.w;
    ((float4*)out)[idx] = o;
}

// ---------------- launcher ---------------------------------------------------
extern "C" void kernel_launch(void* const* d_in, const int* in_sizes, int n_in,
                              void* d_out, int out_size)
{
    const float* x   = (const float*)d_in[0];
    const float* gw  = (const float*)d_in[1];
    const float* egw = (const float*)d_in[2];
    const float* euw = (const float*)d_in[3];
    const float* edw = (const float*)d_in[4];
    const float* sgw = (const float*)d_in[5];
    const float* suw = (const float*)d_in[6];
    const float* sdw = (const float*)d_in[7];
    float* out = (float*)d_out;

    route_kernel<<<T_TOK * 32 / 256, 256>>>(x, gw);
    build_kernel<<<NE, 256>>>();

    swiglu_mma_k<false><<<dim3(ISD / BN, T_TOK / BM, 1), 256>>>(x, sgw, suw, ISD, HD);
    swiglu_mma_k<true ><<<dim3(ID  / BN, T_TOK / BM, NE), 256>>>(x, egw, euw, ID, HD);
    down_mma_k<false><<<dim3(HD / BN, T_TOK / BM, 1), 256>>>(sdw, out, HD, ISD);
    down_mma_k<true ><<<dim3(HD / BN, T_TOK / BM, NE), 256>>>(edw, nullptr, HD, ID);

    combine_kernel<<<(T_TOK * HD / 4) / 256, 256>>>(out);
}